// round 8
// baseline (speedup 1.0000x reference)
#include <cuda_runtime.h>
#include <cuda_bf16.h>
#include <cstdint>

#define S_LEN 2048
#define B_SZ  512
#define HID   64
#define NGATE 256
#define ROWS  4
#define NCTA  (B_SZ / ROWS)   // 128
#define NTHR  256

// Inter-layer hidden state sequences (S, B, H) fp32, flattened row m = t*B + b.
__device__ float g_seq0[S_LEN * B_SZ * HID];
__device__ float g_seq1[S_LEN * B_SZ * HID];
// Precomputed input projections (S, B, 4H) fp32.
__device__ float g_proj[S_LEN * B_SZ * NGATE];

__device__ __forceinline__ float sigm_f(float x) {
    float e = __expf(-x);
    return __fdividef(1.0f, 1.0f + e);
}
__device__ __forceinline__ float tanh_f(float x) {
    float a = fabsf(x);
    float e = __expf(-2.0f * a);
    float t = __fdividef(1.0f - e, 1.0f + e);
    return copysignf(t, x);
}

// ===========================================================================
// Projection GEMM: g_proj[m][n] = sum_k in_seq[m][k] * W[n][k]
// in_seq: (S*B, 64) fp32, W: (256, 64) fp32. bf16x3 split on tensor cores,
// fp32 register accumulators (mma.sync m16n8k16).
// ===========================================================================
#define PM       64            // M rows per CTA
#define WSTRIDE  66            // padded k-stride in bf16 elems (bank spread)
#define SMEM_PROJ ((2 * 256 + 2 * PM) * WSTRIDE * 2)   // 84480 B

__device__ __forceinline__ void mma16816(float c[4], uint32_t a0, uint32_t a1,
                                         uint32_t a2, uint32_t a3,
                                         uint32_t b0, uint32_t b1) {
    asm volatile(
        "mma.sync.aligned.m16n8k16.row.col.f32.bf16.bf16.f32 "
        "{%0,%1,%2,%3},{%4,%5,%6,%7},{%8,%9},{%0,%1,%2,%3};"
        : "+f"(c[0]), "+f"(c[1]), "+f"(c[2]), "+f"(c[3])
        : "r"(a0), "r"(a1), "r"(a2), "r"(a3), "r"(b0), "r"(b1));
}

template <int SRC>   // 0: g_seq0, 1: g_seq1
__global__ __launch_bounds__(NTHR)
void proj_gemm_kernel(const float* __restrict__ Wih)
{
    extern __shared__ __nv_bfloat16 sm[];
    __nv_bfloat16* Whi = sm;
    __nv_bfloat16* Wlo = Whi + 256 * WSTRIDE;
    __nv_bfloat16* Ahi = Wlo + 256 * WSTRIDE;
    __nv_bfloat16* Alo = Ahi + PM * WSTRIDE;

    const float* in_seq = (SRC == 0) ? g_seq0 : g_seq1;
    const int tid = threadIdx.x;
    const int m0  = blockIdx.x * PM;

    // Split W (256x64) into hi/lo bf16
    for (int i = tid; i < 256 * 64; i += NTHR) {
        int n = i >> 6, k = i & 63;
        float w = Wih[i];
        __nv_bfloat16 hi = __float2bfloat16_rn(w);
        Whi[n * WSTRIDE + k] = hi;
        Wlo[n * WSTRIDE + k] = __float2bfloat16_rn(w - __bfloat162float(hi));
    }
    // Split A tile (64x64)
    for (int i = tid; i < PM * 64; i += NTHR) {
        int m = i >> 6, k = i & 63;
        float a = in_seq[(size_t)(m0 + m) * HID + k];
        __nv_bfloat16 hi = __float2bfloat16_rn(a);
        Ahi[m * WSTRIDE + k] = hi;
        Alo[m * WSTRIDE + k] = __float2bfloat16_rn(a - __bfloat162float(hi));
    }
    __syncthreads();

    const int wid = tid >> 5, lane = tid & 31;
    const int wm = (wid & 3) * 16;     // 4 M-warps -> rows wm..wm+15
    const int wn = (wid >> 2) * 128;   // 2 N-warps -> cols wn..wn+127
    const int arow = lane >> 2;        // 0..7
    const int kq   = (lane & 3) * 2;
    const int bn   = lane >> 2;

    float acc[16][4];
    #pragma unroll
    for (int nt = 0; nt < 16; nt++)
        #pragma unroll
        for (int i = 0; i < 4; i++) acc[nt][i] = 0.0f;

    const __nv_bfloat16* Asrc[3] = {Ahi, Ahi, Alo};
    const __nv_bfloat16* Bsrc[3] = {Whi, Wlo, Whi};

    #pragma unroll
    for (int term = 0; term < 3; term++) {
        const __nv_bfloat16* A = Asrc[term];
        const __nv_bfloat16* B = Bsrc[term];
        #pragma unroll
        for (int kc = 0; kc < 4; kc++) {
            const int k0 = kc * 16;
            uint32_t a0 = *(const uint32_t*)&A[(wm + arow    ) * WSTRIDE + k0 + kq];
            uint32_t a1 = *(const uint32_t*)&A[(wm + arow + 8) * WSTRIDE + k0 + kq];
            uint32_t a2 = *(const uint32_t*)&A[(wm + arow    ) * WSTRIDE + k0 + kq + 8];
            uint32_t a3 = *(const uint32_t*)&A[(wm + arow + 8) * WSTRIDE + k0 + kq + 8];
            #pragma unroll
            for (int nt = 0; nt < 16; nt++) {
                const int n = wn + nt * 8 + bn;
                uint32_t b0 = *(const uint32_t*)&B[n * WSTRIDE + k0 + kq];
                uint32_t b1 = *(const uint32_t*)&B[n * WSTRIDE + k0 + kq + 8];
                mma16816(acc[nt], a0, a1, a2, a3, b0, b1);
            }
        }
    }

    // Epilogue: D[m][n], c0/c1 -> (row, 2q..2q+1), c2/c3 -> (row+8, ...)
    const int mrow = m0 + wm + (lane >> 2);
    const int ncol0 = wn + (lane & 3) * 2;
    #pragma unroll
    for (int nt = 0; nt < 16; nt++) {
        const int nc = ncol0 + nt * 8;
        *(float2*)&g_proj[(size_t)mrow * NGATE + nc] =
            make_float2(acc[nt][0], acc[nt][1]);
        *(float2*)&g_proj[(size_t)(mrow + 8) * NGATE + nc] =
            make_float2(acc[nt][2], acc[nt][3]);
    }
}

// ===========================================================================
// Layer 0: external x (B, S, 4) handled in-loop (K=4), writes g_seq0.
// ===========================================================================
__global__ __launch_bounds__(NTHR, 1)
void lstm_l0_kernel(const float* __restrict__ x_ext,
                    const float* __restrict__ Wih,
                    const float* __restrict__ Whh,
                    const float* __restrict__ bih,
                    const float* __restrict__ bhh)
{
    const int tid = threadIdx.x;
    const int b0  = blockIdx.x * ROWS;

    __shared__ __align__(16) float h_s[ROWS][HID];
    __shared__ __align__(16) float x_s[2][ROWS][4];
    __shared__ float gates_s[ROWS][NGATE];

    float whh[HID];
    float wih[4];
    #pragma unroll
    for (int k = 0; k < HID; k++) whh[k] = Whh[tid * HID + k];
    #pragma unroll
    for (int k = 0; k < 4; k++)   wih[k] = Wih[tid * 4 + k];
    const float bsum = bih[tid] + bhh[tid];

    const int urow = tid >> 6, uj = tid & 63;
    h_s[urow][uj] = 0.0f;
    float c_reg = 0.0f;

    const bool xi_act = (tid < ROWS * 4);
    const int  xi_row = tid >> 2;
    const int  xi_k   = tid & 3;

    auto load_x = [&](int t) -> float {
        return xi_act ? x_ext[(size_t)(b0 + xi_row) * (S_LEN * 4) + t * 4 + xi_k]
                      : 0.0f;
    };

    if (xi_act) x_s[0][xi_row][xi_k] = load_x(0);
    __syncthreads();

    for (int t = 0; t < S_LEN; t++) {
        const int par = t & 1;
        float x_next = (t + 1 < S_LEN) ? load_x(t + 1) : 0.0f;

        float acc[ROWS];
        #pragma unroll
        for (int r = 0; r < ROWS; r++) {
            float4 x4 = *reinterpret_cast<const float4*>(&x_s[par][r][0]);
            acc[r] = bsum;
            acc[r] = fmaf(wih[0], x4.x, acc[r]);
            acc[r] = fmaf(wih[1], x4.y, acc[r]);
            acc[r] = fmaf(wih[2], x4.z, acc[r]);
            acc[r] = fmaf(wih[3], x4.w, acc[r]);
        }
        #pragma unroll
        for (int k = 0; k < HID; k += 4) {
            #pragma unroll
            for (int r = 0; r < ROWS; r++) {
                float4 h4 = *reinterpret_cast<const float4*>(&h_s[r][k]);
                acc[r] = fmaf(whh[k + 0], h4.x, acc[r]);
                acc[r] = fmaf(whh[k + 1], h4.y, acc[r]);
                acc[r] = fmaf(whh[k + 2], h4.z, acc[r]);
                acc[r] = fmaf(whh[k + 3], h4.w, acc[r]);
            }
        }
        #pragma unroll
        for (int r = 0; r < ROWS; r++) gates_s[r][tid] = acc[r];
        __syncthreads();

        float gi = gates_s[urow][0 * HID + uj];
        float gf = gates_s[urow][1 * HID + uj];
        float gg = gates_s[urow][2 * HID + uj];
        float go = gates_s[urow][3 * HID + uj];
        float iv = sigm_f(gi), fv = sigm_f(gf), gv = tanh_f(gg), ov = sigm_f(go);
        c_reg = fmaf(fv, c_reg, iv * gv);
        float hv = ov * tanh_f(c_reg);

        h_s[urow][uj] = hv;
        g_seq0[(size_t)(t * B_SZ + b0 + urow) * HID + uj] = hv;
        if (xi_act) x_s[par ^ 1][xi_row][xi_k] = x_next;
        __syncthreads();
    }
}

// ===========================================================================
// Layers 1/2: recurrent-only (K=64), input projection read from g_proj.
// DST: 0 -> g_seq0, 1 -> g_seq1, 2 -> none. FINAL fuses the FC.
// ===========================================================================
template <int DST, bool FINAL>
__global__ __launch_bounds__(NTHR, 1)
void lstm_rec_kernel(const float* __restrict__ Whh,
                     const float* __restrict__ bih,
                     const float* __restrict__ bhh,
                     const float* __restrict__ fc_w,
                     const float* __restrict__ fc_b,
                     float* __restrict__ out_fc)
{
    const int tid = threadIdx.x;
    const int b0  = blockIdx.x * ROWS;
    float* out_seq = (DST == 0) ? g_seq0 : (DST == 1) ? g_seq1 : nullptr;

    __shared__ __align__(16) float h_s[ROWS][HID];
    __shared__ float gates_s[ROWS][NGATE];

    float whh[HID];
    #pragma unroll
    for (int k = 0; k < HID; k++) whh[k] = Whh[tid * HID + k];
    const float bsum = bih[tid] + bhh[tid];

    const int urow = tid >> 6, uj = tid & 63;
    h_s[urow][uj] = 0.0f;
    float c_reg = 0.0f;

    // distance-1 register prefetch of the precomputed projection
    float p_pref[ROWS];
    #pragma unroll
    for (int r = 0; r < ROWS; r++)
        p_pref[r] = g_proj[(size_t)(b0 + r) * NGATE + tid];
    __syncthreads();

    for (int t = 0; t < S_LEN; t++) {
        float acc[ROWS];
        #pragma unroll
        for (int r = 0; r < ROWS; r++) acc[r] = p_pref[r] + bsum;
        if (t + 1 < S_LEN) {
            #pragma unroll
            for (int r = 0; r < ROWS; r++)
                p_pref[r] = g_proj[(size_t)((t + 1) * B_SZ + b0 + r) * NGATE + tid];
        }

        #pragma unroll
        for (int k = 0; k < HID; k += 4) {
            #pragma unroll
            for (int r = 0; r < ROWS; r++) {
                float4 h4 = *reinterpret_cast<const float4*>(&h_s[r][k]);
                acc[r] = fmaf(whh[k + 0], h4.x, acc[r]);
                acc[r] = fmaf(whh[k + 1], h4.y, acc[r]);
                acc[r] = fmaf(whh[k + 2], h4.z, acc[r]);
                acc[r] = fmaf(whh[k + 3], h4.w, acc[r]);
            }
        }
        #pragma unroll
        for (int r = 0; r < ROWS; r++) gates_s[r][tid] = acc[r];
        __syncthreads();

        float gi = gates_s[urow][0 * HID + uj];
        float gf = gates_s[urow][1 * HID + uj];
        float gg = gates_s[urow][2 * HID + uj];
        float go = gates_s[urow][3 * HID + uj];
        float iv = sigm_f(gi), fv = sigm_f(gf), gv = tanh_f(gg), ov = sigm_f(go);
        c_reg = fmaf(fv, c_reg, iv * gv);
        float hv = ov * tanh_f(c_reg);

        h_s[urow][uj] = hv;
        if (DST != 2)
            out_seq[(size_t)(t * B_SZ + b0 + urow) * HID + uj] = hv;
        __syncthreads();
    }

    if (FINAL) {
        if (tid < ROWS * 2) {
            int r = tid >> 1, o = tid & 1;
            float s = fc_b[o];
            #pragma unroll
            for (int j = 0; j < HID; j++)
                s = fmaf(h_s[r][j], fc_w[o * HID + j], s);
            out_fc[(b0 + r) * 2 + o] = s;
        }
    }
}

extern "C" void kernel_launch(void* const* d_in, const int* in_sizes, int n_in,
                              void* d_out, int out_size)
{
    const float* x    = (const float*)d_in[0];
    const float* Wih0 = (const float*)d_in[1];
    const float* Whh0 = (const float*)d_in[2];
    const float* bih0 = (const float*)d_in[3];
    const float* bhh0 = (const float*)d_in[4];
    const float* Wih1 = (const float*)d_in[5];
    const float* Whh1 = (const float*)d_in[6];
    const float* bih1 = (const float*)d_in[7];
    const float* bhh1 = (const float*)d_in[8];
    const float* Wih2 = (const float*)d_in[9];
    const float* Whh2 = (const float*)d_in[10];
    const float* bih2 = (const float*)d_in[11];
    const float* bhh2 = (const float*)d_in[12];
    const float* fc_w = (const float*)d_in[13];
    const float* fc_b = (const float*)d_in[14];
    float* out = (float*)d_out;

    cudaFuncSetAttribute(proj_gemm_kernel<0>,
                         cudaFuncAttributeMaxDynamicSharedMemorySize, SMEM_PROJ);
    cudaFuncSetAttribute(proj_gemm_kernel<1>,
                         cudaFuncAttributeMaxDynamicSharedMemorySize, SMEM_PROJ);

    const int nproj = (S_LEN * B_SZ) / PM;   // 16384

    // layer 0 (K=4 input in-loop) -> g_seq0
    lstm_l0_kernel<<<NCTA, NTHR>>>(x, Wih0, Whh0, bih0, bhh0);
    // proj1 = g_seq0 @ Wih1^T (tensor cores, bf16x3)
    proj_gemm_kernel<0><<<nproj, NTHR, SMEM_PROJ>>>(Wih1);
    // layer 1 recurrence -> g_seq1
    lstm_rec_kernel<1, false><<<NCTA, NTHR>>>(Whh1, bih1, bhh1,
                                              nullptr, nullptr, nullptr);
    // proj2 = g_seq1 @ Wih2^T
    proj_gemm_kernel<1><<<nproj, NTHR, SMEM_PROJ>>>(Wih2);
    // layer 2 recurrence + fused FC -> out
    lstm_rec_kernel<2, true><<<NCTA, NTHR>>>(Whh2, bih2, bhh2,
                                             fc_w, fc_b, out);
}

// round 9
// speedup vs baseline: 1.1477x; 1.1477x over previous
#include <cuda_runtime.h>
#include <cuda_bf16.h>
#include <cstdint>

#define S_LEN 2048
#define B_SZ  512
#define HID   64
#define NGATE 256
#define ROWS  4
#define NCTA  (B_SZ / ROWS)   // 128
#define NTHR  512             // 2 K-halves x 256 gates

// Inter-layer hidden state sequences (S, B, H) fp32, flattened row m = t*B + b.
__device__ float g_seq0[S_LEN * B_SZ * HID];
__device__ float g_seq1[S_LEN * B_SZ * HID];
// Precomputed input projections (S, B, 4H) fp32.
__device__ float g_proj[S_LEN * B_SZ * NGATE];

__device__ __forceinline__ float sigm_f(float x) {
    float e = __expf(-x);
    return __fdividef(1.0f, 1.0f + e);
}
__device__ __forceinline__ float tanh_f(float x) {
    float a = fabsf(x);
    float e = __expf(-2.0f * a);
    float t = __fdividef(1.0f - e, 1.0f + e);
    return copysignf(t, x);
}

// ===========================================================================
// Projection GEMM (unchanged from R8, known-good): g_proj = in_seq @ W^T
// bf16x3 split on tensor cores, fp32 register accumulators.
// ===========================================================================
#define PM       64
#define WSTRIDE  66
#define SMEM_PROJ ((2 * 256 + 2 * PM) * WSTRIDE * 2)

__device__ __forceinline__ void mma16816(float c[4], uint32_t a0, uint32_t a1,
                                         uint32_t a2, uint32_t a3,
                                         uint32_t b0, uint32_t b1) {
    asm volatile(
        "mma.sync.aligned.m16n8k16.row.col.f32.bf16.bf16.f32 "
        "{%0,%1,%2,%3},{%4,%5,%6,%7},{%8,%9},{%0,%1,%2,%3};"
        : "+f"(c[0]), "+f"(c[1]), "+f"(c[2]), "+f"(c[3])
        : "r"(a0), "r"(a1), "r"(a2), "r"(a3), "r"(b0), "r"(b1));
}

template <int SRC>
__global__ __launch_bounds__(256)
void proj_gemm_kernel(const float* __restrict__ Wih)
{
    extern __shared__ __nv_bfloat16 sm[];
    __nv_bfloat16* Whi = sm;
    __nv_bfloat16* Wlo = Whi + 256 * WSTRIDE;
    __nv_bfloat16* Ahi = Wlo + 256 * WSTRIDE;
    __nv_bfloat16* Alo = Ahi + PM * WSTRIDE;

    const float* in_seq = (SRC == 0) ? g_seq0 : g_seq1;
    const int tid = threadIdx.x;
    const int m0  = blockIdx.x * PM;

    for (int i = tid; i < 256 * 64; i += 256) {
        int n = i >> 6, k = i & 63;
        float w = Wih[i];
        __nv_bfloat16 hi = __float2bfloat16_rn(w);
        Whi[n * WSTRIDE + k] = hi;
        Wlo[n * WSTRIDE + k] = __float2bfloat16_rn(w - __bfloat162float(hi));
    }
    for (int i = tid; i < PM * 64; i += 256) {
        int m = i >> 6, k = i & 63;
        float a = in_seq[(size_t)(m0 + m) * HID + k];
        __nv_bfloat16 hi = __float2bfloat16_rn(a);
        Ahi[m * WSTRIDE + k] = hi;
        Alo[m * WSTRIDE + k] = __float2bfloat16_rn(a - __bfloat162float(hi));
    }
    __syncthreads();

    const int wid = tid >> 5, lane = tid & 31;
    const int wm = (wid & 3) * 16;
    const int wn = (wid >> 2) * 128;
    const int arow = lane >> 2;
    const int kq   = (lane & 3) * 2;
    const int bn   = lane >> 2;

    float acc[16][4];
    #pragma unroll
    for (int nt = 0; nt < 16; nt++)
        #pragma unroll
        for (int i = 0; i < 4; i++) acc[nt][i] = 0.0f;

    const __nv_bfloat16* Asrc[3] = {Ahi, Ahi, Alo};
    const __nv_bfloat16* Bsrc[3] = {Whi, Wlo, Whi};

    #pragma unroll
    for (int term = 0; term < 3; term++) {
        const __nv_bfloat16* A = Asrc[term];
        const __nv_bfloat16* B = Bsrc[term];
        #pragma unroll
        for (int kc = 0; kc < 4; kc++) {
            const int k0 = kc * 16;
            uint32_t a0 = *(const uint32_t*)&A[(wm + arow    ) * WSTRIDE + k0 + kq];
            uint32_t a1 = *(const uint32_t*)&A[(wm + arow + 8) * WSTRIDE + k0 + kq];
            uint32_t a2 = *(const uint32_t*)&A[(wm + arow    ) * WSTRIDE + k0 + kq + 8];
            uint32_t a3 = *(const uint32_t*)&A[(wm + arow + 8) * WSTRIDE + k0 + kq + 8];
            #pragma unroll
            for (int nt = 0; nt < 16; nt++) {
                const int n = wn + nt * 8 + bn;
                uint32_t b0 = *(const uint32_t*)&B[n * WSTRIDE + k0 + kq];
                uint32_t b1 = *(const uint32_t*)&B[n * WSTRIDE + k0 + kq + 8];
                mma16816(acc[nt], a0, a1, a2, a3, b0, b1);
            }
        }
    }

    const int mrow = m0 + wm + (lane >> 2);
    const int ncol0 = wn + (lane & 3) * 2;
    #pragma unroll
    for (int nt = 0; nt < 16; nt++) {
        const int nc = ncol0 + nt * 8;
        *(float2*)&g_proj[(size_t)mrow * NGATE + nc] =
            make_float2(acc[nt][0], acc[nt][1]);
        *(float2*)&g_proj[(size_t)(mrow + 8) * NGATE + nc] =
            make_float2(acc[nt][2], acc[nt][3]);
    }
}

// ===========================================================================
// Layer 0: external x (B, S, 4), K split across 2 thread-halves, 512 threads.
// ===========================================================================
__global__ __launch_bounds__(NTHR, 1)
void lstm_l0_kernel(const float* __restrict__ x_ext,
                    const float* __restrict__ Wih,
                    const float* __restrict__ Whh,
                    const float* __restrict__ bih,
                    const float* __restrict__ bhh)
{
    const int tid = threadIdx.x;
    const int g   = tid & 255;      // gate index
    const int kh  = tid >> 8;       // K-half: 0 -> k[0:32), 1 -> k[32:64)
    const int b0  = blockIdx.x * ROWS;

    __shared__ __align__(16) float h_s[ROWS][HID];
    __shared__ __align__(16) float x_s[2][ROWS][4];
    __shared__ float gates_s[2][ROWS][NGATE];

    float whh[32];
    #pragma unroll
    for (int j = 0; j < 32; j++) whh[j] = Whh[g * HID + kh * 32 + j];
    float wih[4];
    #pragma unroll
    for (int j = 0; j < 4; j++) wih[j] = Wih[g * 4 + j];
    const float bsum = (kh == 0) ? (bih[g] + bhh[g]) : 0.0f;

    const int urow = (tid & 255) >> 6, uj = tid & 63;
    if (tid < 256) h_s[urow][uj] = 0.0f;
    float c_reg = 0.0f;

    const bool xi_act = (tid < ROWS * 4);
    const int  xi_row = tid >> 2;
    const int  xi_k   = tid & 3;
    auto load_x = [&](int t) -> float {
        return xi_act ? x_ext[(size_t)(b0 + xi_row) * (S_LEN * 4) + t * 4 + xi_k]
                      : 0.0f;
    };
    if (xi_act) x_s[0][xi_row][xi_k] = load_x(0);
    __syncthreads();

    for (int t = 0; t < S_LEN; t++) {
        const int par = t & 1;
        float x_next = (t + 1 < S_LEN) ? load_x(t + 1) : 0.0f;

        float acc[ROWS];
        #pragma unroll
        for (int r = 0; r < ROWS; r++) {
            acc[r] = bsum;
            if (kh == 0) {
                float4 x4 = *reinterpret_cast<const float4*>(&x_s[par][r][0]);
                acc[r] = fmaf(wih[0], x4.x, acc[r]);
                acc[r] = fmaf(wih[1], x4.y, acc[r]);
                acc[r] = fmaf(wih[2], x4.z, acc[r]);
                acc[r] = fmaf(wih[3], x4.w, acc[r]);
            }
        }
        #pragma unroll
        for (int j = 0; j < 32; j += 4) {
            #pragma unroll
            for (int r = 0; r < ROWS; r++) {
                float4 h4 = *reinterpret_cast<const float4*>(&h_s[r][kh * 32 + j]);
                acc[r] = fmaf(whh[j + 0], h4.x, acc[r]);
                acc[r] = fmaf(whh[j + 1], h4.y, acc[r]);
                acc[r] = fmaf(whh[j + 2], h4.z, acc[r]);
                acc[r] = fmaf(whh[j + 3], h4.w, acc[r]);
            }
        }
        #pragma unroll
        for (int r = 0; r < ROWS; r++) gates_s[kh][r][g] = acc[r];
        __syncthreads();

        if (tid < 256) {
            float gi = gates_s[0][urow][0 * HID + uj] + gates_s[1][urow][0 * HID + uj];
            float gf = gates_s[0][urow][1 * HID + uj] + gates_s[1][urow][1 * HID + uj];
            float gg = gates_s[0][urow][2 * HID + uj] + gates_s[1][urow][2 * HID + uj];
            float go = gates_s[0][urow][3 * HID + uj] + gates_s[1][urow][3 * HID + uj];
            float iv = sigm_f(gi), fv = sigm_f(gf), gv = tanh_f(gg), ov = sigm_f(go);
            c_reg = fmaf(fv, c_reg, iv * gv);
            float hv = ov * tanh_f(c_reg);
            h_s[urow][uj] = hv;
            g_seq0[(size_t)(t * B_SZ + b0 + urow) * HID + uj] = hv;
        }
        if (xi_act) x_s[par ^ 1][xi_row][xi_k] = x_next;
        __syncthreads();
    }
}

// ===========================================================================
// Layers 1/2: recurrent-only, K split across 2 thread-halves, 512 threads.
// DST: 0 -> g_seq0, 1 -> g_seq1, 2 -> none. FINAL fuses the FC.
// ===========================================================================
template <int DST, bool FINAL>
__global__ __launch_bounds__(NTHR, 1)
void lstm_rec_kernel(const float* __restrict__ Whh,
                     const float* __restrict__ bih,
                     const float* __restrict__ bhh,
                     const float* __restrict__ fc_w,
                     const float* __restrict__ fc_b,
                     float* __restrict__ out_fc)
{
    const int tid = threadIdx.x;
    const int g   = tid & 255;
    const int kh  = tid >> 8;
    const int b0  = blockIdx.x * ROWS;
    float* out_seq = (DST == 0) ? g_seq0 : (DST == 1) ? g_seq1 : nullptr;

    __shared__ __align__(16) float h_s[ROWS][HID];
    __shared__ float gates_s[2][ROWS][NGATE];

    float whh[32];
    #pragma unroll
    for (int j = 0; j < 32; j++) whh[j] = Whh[g * HID + kh * 32 + j];
    const float bsum = (kh == 0) ? (bih[g] + bhh[g]) : 0.0f;

    const int urow = (tid & 255) >> 6, uj = tid & 63;
    if (tid < 256) h_s[urow][uj] = 0.0f;
    float c_reg = 0.0f;

    // distance-1 register prefetch of the precomputed projection (half 0 only)
    float p_pref[ROWS];
    #pragma unroll
    for (int r = 0; r < ROWS; r++)
        p_pref[r] = (kh == 0) ? g_proj[(size_t)(b0 + r) * NGATE + g] : 0.0f;
    __syncthreads();

    for (int t = 0; t < S_LEN; t++) {
        float acc[ROWS];
        #pragma unroll
        for (int r = 0; r < ROWS; r++) acc[r] = p_pref[r] + bsum;
        if (kh == 0 && t + 1 < S_LEN) {
            #pragma unroll
            for (int r = 0; r < ROWS; r++)
                p_pref[r] = g_proj[(size_t)((t + 1) * B_SZ + b0 + r) * NGATE + g];
        }

        #pragma unroll
        for (int j = 0; j < 32; j += 4) {
            #pragma unroll
            for (int r = 0; r < ROWS; r++) {
                float4 h4 = *reinterpret_cast<const float4*>(&h_s[r][kh * 32 + j]);
                acc[r] = fmaf(whh[j + 0], h4.x, acc[r]);
                acc[r] = fmaf(whh[j + 1], h4.y, acc[r]);
                acc[r] = fmaf(whh[j + 2], h4.z, acc[r]);
                acc[r] = fmaf(whh[j + 3], h4.w, acc[r]);
            }
        }
        #pragma unroll
        for (int r = 0; r < ROWS; r++) gates_s[kh][r][g] = acc[r];
        __syncthreads();

        if (tid < 256) {
            float gi = gates_s[0][urow][0 * HID + uj] + gates_s[1][urow][0 * HID + uj];
            float gf = gates_s[0][urow][1 * HID + uj] + gates_s[1][urow][1 * HID + uj];
            float gg = gates_s[0][urow][2 * HID + uj] + gates_s[1][urow][2 * HID + uj];
            float go = gates_s[0][urow][3 * HID + uj] + gates_s[1][urow][3 * HID + uj];
            float iv = sigm_f(gi), fv = sigm_f(gf), gv = tanh_f(gg), ov = sigm_f(go);
            c_reg = fmaf(fv, c_reg, iv * gv);
            float hv = ov * tanh_f(c_reg);
            h_s[urow][uj] = hv;
            if (DST != 2)
                out_seq[(size_t)(t * B_SZ + b0 + urow) * HID + uj] = hv;
        }
        __syncthreads();
    }

    if (FINAL) {
        if (tid < ROWS * 2) {
            int r = tid >> 1, o = tid & 1;
            float s = fc_b[o];
            #pragma unroll
            for (int j = 0; j < HID; j++)
                s = fmaf(h_s[r][j], fc_w[o * HID + j], s);
            out_fc[(b0 + r) * 2 + o] = s;
        }
    }
}

extern "C" void kernel_launch(void* const* d_in, const int* in_sizes, int n_in,
                              void* d_out, int out_size)
{
    const float* x    = (const float*)d_in[0];
    const float* Wih0 = (const float*)d_in[1];
    const float* Whh0 = (const float*)d_in[2];
    const float* bih0 = (const float*)d_in[3];
    const float* bhh0 = (const float*)d_in[4];
    const float* Wih1 = (const float*)d_in[5];
    const float* Whh1 = (const float*)d_in[6];
    const float* bih1 = (const float*)d_in[7];
    const float* bhh1 = (const float*)d_in[8];
    const float* Wih2 = (const float*)d_in[9];
    const float* Whh2 = (const float*)d_in[10];
    const float* bih2 = (const float*)d_in[11];
    const float* bhh2 = (const float*)d_in[12];
    const float* fc_w = (const float*)d_in[13];
    const float* fc_b = (const float*)d_in[14];
    float* out = (float*)d_out;

    cudaFuncSetAttribute(proj_gemm_kernel<0>,
                         cudaFuncAttributeMaxDynamicSharedMemorySize, SMEM_PROJ);
    cudaFuncSetAttribute(proj_gemm_kernel<1>,
                         cudaFuncAttributeMaxDynamicSharedMemorySize, SMEM_PROJ);

    const int nproj = (S_LEN * B_SZ) / PM;   // 16384

    lstm_l0_kernel<<<NCTA, NTHR>>>(x, Wih0, Whh0, bih0, bhh0);
    proj_gemm_kernel<0><<<nproj, 256, SMEM_PROJ>>>(Wih1);
    lstm_rec_kernel<1, false><<<NCTA, NTHR>>>(Whh1, bih1, bhh1,
                                              nullptr, nullptr, nullptr);
    proj_gemm_kernel<1><<<nproj, 256, SMEM_PROJ>>>(Wih2);
    lstm_rec_kernel<2, true><<<NCTA, NTHR>>>(Whh2, bih2, bhh2,
                                             fc_w, fc_b, out);
}